// round 14
// baseline (speedup 1.0000x reference)
#include <cuda_runtime.h>
#include <cuda_fp16.h>
#include <cstdint>

#define N_NODES  100000
#define N_EDGES  1600000
#define CH       128
#define OUTC     64
#define N_GRAPHS 256
#define SCAN_BLK 1024
#define SCAN_NB  ((N_NODES + SCAN_BLK - 1) / SCAN_BLK)   // 98

#define BM2  128          // GEMM block tile M
#define PAD2 72           // smem row stride in u32 (64 half2 + pad), conflict-free
// B-fragment table (fp16): [layer][wn][ks][lane][ni][j] = 3*2*8*32*8*2 u32
#define BFRAG_PER_LAYER (2 * 8 * 32 * 8 * 2)

// ---------------- scratch (alloc-free rule: __device__ globals) ----------------
__device__ __align__(16) __half g_xh [(size_t)N_NODES * CH];   // fp16 copy of x
__device__ __align__(16) __half g_h  [(size_t)N_NODES * CH];   // fp16 activations (ping)
__device__ __align__(16) __half g_h2 [(size_t)N_NODES * CH];   // fp16 activations (pong)
__device__ __align__(16) float g_pool[N_GRAPHS * CH];
__device__ float g_cnt[N_GRAPHS];
__device__ int   g_idx64;
__device__ int   g_deg[N_NODES];
__device__ int   g_rowptr[N_NODES + 1];
__device__ int   g_cursor[N_NODES];
__device__ int   g_esrc[N_EDGES];
__device__ int   g_blocksum[SCAN_NB];
__device__ __align__(16) uint32_t g_bfrag[3 * BFRAG_PER_LAYER];

// ---------------- helpers ----------------
__device__ __forceinline__ long long load_idx(const void* buf, long long i, int is64) {
    if (is64) return ((const long long*)buf)[i];
    return (long long)((const int*)buf)[i];
}

__device__ __forceinline__ float4 h4f(uint2 v) {
    float2 a = __half22float2(*reinterpret_cast<__half2*>(&v.x));
    float2 b = __half22float2(*reinterpret_cast<__half2*>(&v.y));
    return make_float4(a.x, a.y, b.x, b.y);
}

__global__ void detect_kernel(const int* __restrict__ ei_raw) {
    int nz = 0;
#pragma unroll 8
    for (int i = 0; i < 1024; i++) nz |= ei_raw[2 * i + 1];
    g_idx64 = (nz == 0) ? 1 : 0;
}

// x (fp32) -> g_xh (fp16)
__global__ void xconv_kernel(const float2* __restrict__ x2) {
    int i = blockIdx.x * blockDim.x + threadIdx.x;
    if (i >= N_NODES * CH / 2) return;
    float2 v = __ldg(&x2[i]);
    __half2 h = __floats2half2_rn(v.x, v.y);
    reinterpret_cast<__half2*>(g_xh)[i] = h;
}

// ---------------- CSR build ----------------
__global__ void zero_deg_kernel() {
    int i = blockIdx.x * blockDim.x + threadIdx.x;
    if (i < N_NODES) g_deg[i] = 0;
}

// 4 edges per thread, int4 loads on the int32 path
__global__ void hist_kernel(const void* __restrict__ ei) {
    int t = blockIdx.x * blockDim.x + threadIdx.x;
    int e0 = t * 4;
    if (e0 >= N_EDGES) return;
    if (!g_idx64) {
        int4 d4 = __ldg(reinterpret_cast<const int4*>((const int*)ei + N_EDGES) + t);
        atomicAdd(&g_deg[d4.x], 1);
        atomicAdd(&g_deg[d4.y], 1);
        atomicAdd(&g_deg[d4.z], 1);
        atomicAdd(&g_deg[d4.w], 1);
    } else {
#pragma unroll
        for (int q = 0; q < 4; q++) {
            int d = (int)((const long long*)ei)[(long long)N_EDGES + e0 + q];
            atomicAdd(&g_deg[d], 1);
        }
    }
}

__global__ void scan1_kernel() {
    __shared__ int sm[SCAN_BLK];
    int i = blockIdx.x * SCAN_BLK + threadIdx.x;
    int v = (i < N_NODES) ? g_deg[i] : 0;
    sm[threadIdx.x] = v;
    __syncthreads();
    for (int off = 1; off < SCAN_BLK; off <<= 1) {
        int t = (threadIdx.x >= off) ? sm[threadIdx.x - off] : 0;
        __syncthreads();
        sm[threadIdx.x] += t;
        __syncthreads();
    }
    if (i < N_NODES) g_rowptr[i] = sm[threadIdx.x] - v;
    if (threadIdx.x == SCAN_BLK - 1) g_blocksum[blockIdx.x] = sm[SCAN_BLK - 1];
}

__global__ void scan2_kernel() {
    if (threadIdx.x != 0) return;
    int run = 0;
    for (int b = 0; b < SCAN_NB; b++) { int t = g_blocksum[b]; g_blocksum[b] = run; run += t; }
    g_rowptr[N_NODES] = N_EDGES;
}

__global__ void scan3_kernel() {
    int i = blockIdx.x * blockDim.x + threadIdx.x;
    if (i >= N_NODES) return;
    int r = g_rowptr[i] + g_blocksum[i >> 10];
    g_rowptr[i] = r;
    g_cursor[i] = r;
}

__global__ void fill_kernel(const void* __restrict__ ei) {
    int t = blockIdx.x * blockDim.x + threadIdx.x;
    int e0 = t * 4;
    if (e0 >= N_EDGES) return;
    if (!g_idx64) {
        int4 s4 = __ldg(reinterpret_cast<const int4*>((const int*)ei) + t);
        int4 d4 = __ldg(reinterpret_cast<const int4*>((const int*)ei + N_EDGES) + t);
        g_esrc[atomicAdd(&g_cursor[d4.x], 1)] = s4.x;
        g_esrc[atomicAdd(&g_cursor[d4.y], 1)] = s4.y;
        g_esrc[atomicAdd(&g_cursor[d4.z], 1)] = s4.z;
        g_esrc[atomicAdd(&g_cursor[d4.w], 1)] = s4.w;
    } else {
#pragma unroll
        for (int q = 0; q < 4; q++) {
            int s = (int)((const long long*)ei)[e0 + q];
            int d = (int)((const long long*)ei)[(long long)N_EDGES + e0 + q];
            g_esrc[atomicAdd(&g_cursor[d], 1)] = s;
        }
    }
}

// ---------------- fp16 B-fragment precompute ----------------
__global__ void wfrag_kernel(const float* __restrict__ W0, const float* __restrict__ W1,
                             const float* __restrict__ W2) {
    int idx = blockIdx.x * blockDim.x + threadIdx.x;
    if (idx >= 3 * BFRAG_PER_LAYER) return;
    int j    = idx & 1;
    int ni   = (idx >> 1) & 7;
    int lane = (idx >> 4) & 31;
    int ks   = (idx >> 9) & 7;
    int wn   = (idx >> 12) & 1;
    int l    = idx >> 13;
    int n  = wn * 64 + ni * 8 + (lane >> 2);
    int k0 = ks * 16 + 2 * (lane & 3) + j * 8;
    const float* W = (l == 0) ? W0 : ((l == 1) ? W1 : W2);
    __half2 h = __floats2half2_rn(__ldg(&W[k0 * CH + n]), __ldg(&W[(k0 + 1) * CH + n]));
    g_bfrag[idx] = *reinterpret_cast<uint32_t*>(&h);
}

// ---------------- fused aggregate + fp16 GEMM ----------------
// X and H MUST be distinct buffers (gather reads arbitrary X rows while other
// blocks write H). Phase 1: each warp aggregates 16 rows into the permuted smem
// A-tile. Phase 2: mma mainloop + bias/relu epilogue -> fp16 H.
__global__ __launch_bounds__(256, 4)
void fused_agg_gemm_kernel(const __half* __restrict__ X, const uint4* __restrict__ bfrag4,
                           const float* __restrict__ bias, __half* __restrict__ H, int M) {
    extern __shared__ uint32_t As[];     // BM2 * PAD2 (half2 units, permuted)
    int tid = threadIdx.x;               // 256
    int row0 = blockIdx.x * BM2;
    int lane = tid & 31;
    int w    = tid >> 5;                 // warp 0..7

    // permuted half2 positions for this lane (c2 = 2*lane, 2*lane+1)
    int c2a = 2 * lane;
    int pa = (c2a & ~7) + (c2a & 3) * 2 + ((c2a >> 2) & 1);
    int c2b = 2 * lane + 1;
    int pb = (c2b & ~7) + (c2b & 3) * 2 + ((c2b >> 2) & 1);

    const uint2* Xr = reinterpret_cast<const uint2*>(X);   // 32 uint2 per row

    // ---- phase 1: aggregate 16 rows per warp into smem
    for (int t = 0; t < 16; t++) {
        int r = w * 16 + t;              // row in tile
        int node = row0 + r;
        uint32_t ha = 0, hb = 0;
        if (node < M) {
            int beg = __ldg(&g_rowptr[node]);
            int end = __ldg(&g_rowptr[node + 1]);
            float4 acc = h4f(__ldg(&Xr[(size_t)node * 32 + lane]));
            int e = beg;
            for (; e + 1 < end; e += 2) {
                int s0 = __ldg(&g_esrc[e]);
                int s1 = __ldg(&g_esrc[e + 1]);
                float4 v0 = h4f(__ldg(&Xr[(size_t)s0 * 32 + lane]));
                float4 v1 = h4f(__ldg(&Xr[(size_t)s1 * 32 + lane]));
                acc.x += v0.x + v1.x; acc.y += v0.y + v1.y;
                acc.z += v0.z + v1.z; acc.w += v0.w + v1.w;
            }
            if (e < end) {
                int s = __ldg(&g_esrc[e]);
                float4 v = h4f(__ldg(&Xr[(size_t)s * 32 + lane]));
                acc.x += v.x; acc.y += v.y; acc.z += v.z; acc.w += v.w;
            }
            __half2 lo = __floats2half2_rn(acc.x, acc.y);
            __half2 hi = __floats2half2_rn(acc.z, acc.w);
            ha = *reinterpret_cast<uint32_t*>(&lo);
            hb = *reinterpret_cast<uint32_t*>(&hi);
        }
        As[r * PAD2 + pa] = ha;
        As[r * PAD2 + pb] = hb;
    }
    __syncthreads();

    // ---- phase 2: GEMM mainloop
    int wm = w & 3;         // 4 warps along M (32 rows each)
    int wn = w >> 2;        // 2 warps along N (64 cols each)

    float c[2][8][4];
#pragma unroll
    for (int mi = 0; mi < 2; mi++)
#pragma unroll
        for (int ni = 0; ni < 8; ni++)
#pragma unroll
            for (int j = 0; j < 4; j++) c[mi][ni][j] = 0.f;

    const uint4* bwarp = bfrag4 + ((size_t)wn * 8) * 128 + lane * 4;
    const uint32_t* a_base = As + (wm * 32 + (lane >> 2)) * PAD2 + (lane & 3) * 2;

#pragma unroll
    for (int ks = 0; ks < 8; ks++) {
        uint2 ar0 = *reinterpret_cast<const uint2*>(a_base + ks * 8);
        uint2 ar8 = *reinterpret_cast<const uint2*>(a_base + 8 * PAD2 + ks * 8);
        uint2 br0 = *reinterpret_cast<const uint2*>(a_base + 16 * PAD2 + ks * 8);
        uint2 br8 = *reinterpret_cast<const uint2*>(a_base + 24 * PAD2 + ks * 8);
        const uint4* p = bwarp + ks * 128;
#pragma unroll
        for (int q = 0; q < 4; q++) {
            uint4 bv = __ldg(p + q);
            asm volatile(
                "mma.sync.aligned.m16n8k16.row.col.f32.f16.f16.f32 "
                "{%0,%1,%2,%3}, {%4,%5,%6,%7}, {%8,%9}, {%0,%1,%2,%3};"
                : "+f"(c[0][2*q][0]), "+f"(c[0][2*q][1]), "+f"(c[0][2*q][2]), "+f"(c[0][2*q][3])
                : "r"(ar0.x), "r"(ar8.x), "r"(ar0.y), "r"(ar8.y), "r"(bv.x), "r"(bv.y));
            asm volatile(
                "mma.sync.aligned.m16n8k16.row.col.f32.f16.f16.f32 "
                "{%0,%1,%2,%3}, {%4,%5,%6,%7}, {%8,%9}, {%0,%1,%2,%3};"
                : "+f"(c[1][2*q][0]), "+f"(c[1][2*q][1]), "+f"(c[1][2*q][2]), "+f"(c[1][2*q][3])
                : "r"(br0.x), "r"(br8.x), "r"(br0.y), "r"(br8.y), "r"(bv.x), "r"(bv.y));
            asm volatile(
                "mma.sync.aligned.m16n8k16.row.col.f32.f16.f16.f32 "
                "{%0,%1,%2,%3}, {%4,%5,%6,%7}, {%8,%9}, {%0,%1,%2,%3};"
                : "+f"(c[0][2*q+1][0]), "+f"(c[0][2*q+1][1]), "+f"(c[0][2*q+1][2]), "+f"(c[0][2*q+1][3])
                : "r"(ar0.x), "r"(ar8.x), "r"(ar0.y), "r"(ar8.y), "r"(bv.z), "r"(bv.w));
            asm volatile(
                "mma.sync.aligned.m16n8k16.row.col.f32.f16.f16.f32 "
                "{%0,%1,%2,%3}, {%4,%5,%6,%7}, {%8,%9}, {%0,%1,%2,%3};"
                : "+f"(c[1][2*q+1][0]), "+f"(c[1][2*q+1][1]), "+f"(c[1][2*q+1][2]), "+f"(c[1][2*q+1][3])
                : "r"(br0.x), "r"(br8.x), "r"(br0.y), "r"(br8.y), "r"(bv.z), "r"(bv.w));
        }
    }

    // ---- epilogue: bias + relu -> half2 stores
#pragma unroll
    for (int mi = 0; mi < 2; mi++) {
#pragma unroll
        for (int ni = 0; ni < 8; ni++) {
            int col = wn * 64 + ni * 8 + 2 * (lane & 3);
            float bx = __ldg(&bias[col]), by = __ldg(&bias[col + 1]);
            int r = row0 + wm * 32 + mi * 16 + (lane >> 2);
            if (r < M) {
                __half2 o = __floats2half2_rn(fmaxf(c[mi][ni][0] + bx, 0.f),
                                              fmaxf(c[mi][ni][1] + by, 0.f));
                *reinterpret_cast<__half2*>(H + (size_t)r * CH + col) = o;
            }
            if (r + 8 < M) {
                __half2 o = __floats2half2_rn(fmaxf(c[mi][ni][2] + bx, 0.f),
                                              fmaxf(c[mi][ni][3] + by, 0.f));
                *reinterpret_cast<__half2*>(H + (size_t)(r + 8) * CH + col) = o;
            }
        }
    }
}

// ---------------- pooling + classifier ----------------
__global__ void zero_pool_kernel() {
    int i = blockIdx.x * blockDim.x + threadIdx.x;
    if (i < N_GRAPHS * CH) g_pool[i] = 0.f;
}

__global__ void counts_kernel(const void* __restrict__ batch) {
    int g = blockIdx.x * blockDim.x + threadIdx.x;
    if (g >= N_GRAPHS) return;
    int is64 = g_idx64;
    int lo = 0, hi = N_NODES;
    while (lo < hi) { int m = (lo + hi) >> 1; if (load_idx(batch, m, is64) < g) lo = m + 1; else hi = m; }
    int lb = lo;
    lo = 0; hi = N_NODES;
    while (lo < hi) { int m = (lo + hi) >> 1; if (load_idx(batch, m, is64) <= g) lo = m + 1; else hi = m; }
    g_cnt[g] = (float)(lo - lb);
}

__global__ void pool_kernel(const __half* __restrict__ Hm, const void* __restrict__ batch) {
    int c = threadIdx.x;  // 0..127
    int start = blockIdx.x * 128;
    int end = min(start + 128, N_NODES);
    if (start >= N_NODES) return;
    int is64 = g_idx64;
    long long cur = load_idx(batch, start, is64);
    float sum = 0.f;
    for (int i = start; i < end; i++) {
        long long g = load_idx(batch, i, is64);
        if (g != cur) {
            atomicAdd(&g_pool[(int)cur * CH + c], sum);
            sum = 0.f; cur = g;
        }
        sum += __half2float(Hm[(size_t)i * CH + c]);
    }
    atomicAdd(&g_pool[(int)cur * CH + c], sum);
}

__global__ void final_kernel(const float* __restrict__ Wf, const float* __restrict__ bf,
                             float* __restrict__ out) {
    int g = blockIdx.x;
    int o = threadIdx.x;  // 0..63
    float inv = 1.f / fmaxf(g_cnt[g], 1.f);
    float s = 0.f;
#pragma unroll 8
    for (int k = 0; k < CH; k++)
        s = fmaf(g_pool[g * CH + k], __ldg(&Wf[k * OUTC + o]), s);
    out[g * OUTC + o] = s * inv + bf[o];
}

// ---------------- launch ----------------
extern "C" void kernel_launch(void* const* d_in, const int* in_sizes, int n_in,
                              void* d_out, int out_size) {
    const float* x = nullptr;
    const void* ei = nullptr;
    const void* batch = nullptr;
    const float* Wm[3] = {nullptr, nullptr, nullptr};
    const float* Bv[3] = {nullptr, nullptr, nullptr};
    const float* Wf = nullptr;
    const float* bf = nullptr;
    int wi = 0, bi = 0;
    for (int i = 0; i < n_in; i++) {
        switch (in_sizes[i]) {
            case N_NODES * CH:      x     = (const float*)d_in[i]; break;
            case 2 * N_EDGES:       ei    = d_in[i]; break;
            case N_NODES:           batch = d_in[i]; break;
            case CH * CH:           if (wi < 3) Wm[wi++] = (const float*)d_in[i]; break;
            case CH:                if (bi < 3) Bv[bi++] = (const float*)d_in[i]; break;
            case CH * OUTC:         Wf    = (const float*)d_in[i]; break;
            case OUTC:              bf    = (const float*)d_in[i]; break;
            default: break;
        }
    }
    float* out = (float*)d_out;

    size_t smem = (size_t)(BM2 * PAD2) * sizeof(uint32_t);   // 36864
    cudaFuncSetAttribute(fused_agg_gemm_kernel, cudaFuncAttributeMaxDynamicSharedMemorySize, (int)smem);

    __half* xh_p;  cudaGetSymbolAddress((void**)&xh_p,  g_xh);
    __half* h_p;   cudaGetSymbolAddress((void**)&h_p,   g_h);
    __half* h2_p;  cudaGetSymbolAddress((void**)&h2_p,  g_h2);
    uint32_t* bfrag_p; cudaGetSymbolAddress((void**)&bfrag_p, g_bfrag);

    const int node_blocks  = (N_NODES + 255) / 256;
    const int edge4_blocks = (N_EDGES / 4 + 255) / 256;
    const int gemm_blocks  = (N_NODES + BM2 - 1) / BM2;

    // ---- once-per-launch prep
    detect_kernel<<<1, 1>>>((const int*)ei);
    xconv_kernel<<<(N_NODES * CH / 2 + 255) / 256, 256>>>((const float2*)x);
    zero_deg_kernel<<<node_blocks, 256>>>();
    hist_kernel<<<edge4_blocks, 256>>>(ei);
    scan1_kernel<<<SCAN_NB, SCAN_BLK>>>();
    scan2_kernel<<<1, 32>>>();
    scan3_kernel<<<node_blocks, 256>>>();
    fill_kernel<<<edge4_blocks, 256>>>(ei);
    wfrag_kernel<<<(3 * BFRAG_PER_LAYER + 255) / 256, 256>>>(Wm[0], Wm[1], Wm[2]);

    // ---- 3 fused layers (ping-pong: distinct src/dst each launch)
    fused_agg_gemm_kernel<<<gemm_blocks, 256, smem>>>(xh_p, (const uint4*)(bfrag_p), Bv[0], h_p, N_NODES);
    fused_agg_gemm_kernel<<<gemm_blocks, 256, smem>>>(h_p, (const uint4*)(bfrag_p + BFRAG_PER_LAYER), Bv[1], h2_p, N_NODES);
    fused_agg_gemm_kernel<<<gemm_blocks, 256, smem>>>(h2_p, (const uint4*)(bfrag_p + 2 * BFRAG_PER_LAYER), Bv[2], h_p, N_NODES);

    // ---- pooling + classifier
    zero_pool_kernel<<<(N_GRAPHS * CH + 255) / 256, 256>>>();
    counts_kernel<<<1, N_GRAPHS>>>(batch);
    pool_kernel<<<(N_NODES + 127) / 128, 128>>>(h_p, batch);
    final_kernel<<<N_GRAPHS, OUTC>>>(Wf, bf, out);

    (void)n_in; (void)out_size;
}

// round 17
// speedup vs baseline: 1.4479x; 1.4479x over previous
#include <cuda_runtime.h>
#include <cuda_fp16.h>
#include <cstdint>

#define N_NODES  100000
#define N_EDGES  1600000
#define CH       128
#define OUTC     64
#define N_GRAPHS 256
#define SCAN_BLK 1024
#define SCAN_NB  ((N_NODES + SCAN_BLK - 1) / SCAN_BLK)   // 98

#define BM2  128          // GEMM block tile M
#define PAD2 72           // smem row stride in u32 (64 half2 + pad), conflict-free
// B-fragment table (fp16): [layer][wn][ks][lane][ni][j] = 3*2*8*32*8*2 u32
#define BFRAG_PER_LAYER (2 * 8 * 32 * 8 * 2)

// ---------------- scratch (alloc-free rule: __device__ globals) ----------------
__device__ __align__(16) __half g_xh [(size_t)N_NODES * CH];   // fp16 copy of x
__device__ __align__(16) __half g_agg[(size_t)N_NODES * CH];   // fp16 agg
__device__ __align__(16) __half g_h  [(size_t)N_NODES * CH];   // fp16 activations
__device__ __align__(16) float g_pool[N_GRAPHS * CH];
__device__ float g_cnt[N_GRAPHS];
__device__ int   g_idx64;
__device__ int   g_deg[N_NODES];
__device__ int   g_rowptr[N_NODES + 1];
__device__ int   g_cursor[N_NODES];
__device__ int   g_esrc[N_EDGES];
__device__ int   g_blocksum[SCAN_NB];
__device__ __align__(16) uint32_t g_bfrag[3 * BFRAG_PER_LAYER];

// ---------------- helpers ----------------
__device__ __forceinline__ long long load_idx(const void* buf, long long i, int is64) {
    if (is64) return ((const long long*)buf)[i];
    return (long long)((const int*)buf)[i];
}

__device__ __forceinline__ float2 h2f2(uint32_t u) {
    return __half22float2(*reinterpret_cast<__half2*>(&u));
}
__device__ __forceinline__ uint32_t f22h2(float x, float y) {
    __half2 h = __floats2half2_rn(x, y);
    return *reinterpret_cast<uint32_t*>(&h);
}

__global__ void detect_kernel(const int* __restrict__ ei_raw) {
    int nz = 0;
#pragma unroll 8
    for (int i = 0; i < 1024; i++) nz |= ei_raw[2 * i + 1];
    g_idx64 = (nz == 0) ? 1 : 0;
}

// x (fp32) -> g_xh (fp16)
__global__ void xconv_kernel(const float2* __restrict__ x2) {
    int i = blockIdx.x * blockDim.x + threadIdx.x;
    if (i >= N_NODES * CH / 2) return;
    float2 v = __ldg(&x2[i]);
    __half2 h = __floats2half2_rn(v.x, v.y);
    reinterpret_cast<__half2*>(g_xh)[i] = h;
}

// ---------------- CSR build ----------------
__global__ void zero_deg_kernel() {
    int i = blockIdx.x * blockDim.x + threadIdx.x;
    if (i < N_NODES) g_deg[i] = 0;
}

// 4 edges per thread, int4 loads on the int32 path
__global__ void hist_kernel(const void* __restrict__ ei) {
    int t = blockIdx.x * blockDim.x + threadIdx.x;
    int e0 = t * 4;
    if (e0 >= N_EDGES) return;
    if (!g_idx64) {
        int4 d4 = __ldg(reinterpret_cast<const int4*>((const int*)ei + N_EDGES) + t);
        atomicAdd(&g_deg[d4.x], 1);
        atomicAdd(&g_deg[d4.y], 1);
        atomicAdd(&g_deg[d4.z], 1);
        atomicAdd(&g_deg[d4.w], 1);
    } else {
#pragma unroll
        for (int q = 0; q < 4; q++) {
            int d = (int)((const long long*)ei)[(long long)N_EDGES + e0 + q];
            atomicAdd(&g_deg[d], 1);
        }
    }
}

__global__ void scan1_kernel() {
    __shared__ int sm[SCAN_BLK];
    int i = blockIdx.x * SCAN_BLK + threadIdx.x;
    int v = (i < N_NODES) ? g_deg[i] : 0;
    sm[threadIdx.x] = v;
    __syncthreads();
    for (int off = 1; off < SCAN_BLK; off <<= 1) {
        int t = (threadIdx.x >= off) ? sm[threadIdx.x - off] : 0;
        __syncthreads();
        sm[threadIdx.x] += t;
        __syncthreads();
    }
    if (i < N_NODES) g_rowptr[i] = sm[threadIdx.x] - v;
    if (threadIdx.x == SCAN_BLK - 1) g_blocksum[blockIdx.x] = sm[SCAN_BLK - 1];
}

__global__ void scan2_kernel() {
    if (threadIdx.x != 0) return;
    int run = 0;
    for (int b = 0; b < SCAN_NB; b++) { int t = g_blocksum[b]; g_blocksum[b] = run; run += t; }
    g_rowptr[N_NODES] = N_EDGES;
}

__global__ void scan3_kernel() {
    int i = blockIdx.x * blockDim.x + threadIdx.x;
    if (i >= N_NODES) return;
    int r = g_rowptr[i] + g_blocksum[i >> 10];
    g_rowptr[i] = r;
    g_cursor[i] = r;
}

__global__ void fill_kernel(const void* __restrict__ ei) {
    int t = blockIdx.x * blockDim.x + threadIdx.x;
    int e0 = t * 4;
    if (e0 >= N_EDGES) return;
    if (!g_idx64) {
        int4 s4 = __ldg(reinterpret_cast<const int4*>((const int*)ei) + t);
        int4 d4 = __ldg(reinterpret_cast<const int4*>((const int*)ei + N_EDGES) + t);
        g_esrc[atomicAdd(&g_cursor[d4.x], 1)] = s4.x;
        g_esrc[atomicAdd(&g_cursor[d4.y], 1)] = s4.y;
        g_esrc[atomicAdd(&g_cursor[d4.z], 1)] = s4.z;
        g_esrc[atomicAdd(&g_cursor[d4.w], 1)] = s4.w;
    } else {
#pragma unroll
        for (int q = 0; q < 4; q++) {
            int s = (int)((const long long*)ei)[e0 + q];
            int d = (int)((const long long*)ei)[(long long)N_EDGES + e0 + q];
            g_esrc[atomicAdd(&g_cursor[d], 1)] = s;
        }
    }
}

// ---------------- aggregation: half-warp per node, LDG.128 rows ----------------
// out[n,:] = X[n,:] + sum_{s in N(n)} X[s,:]; 16 lanes x uint4 = 256B row
__global__ void aggregate_kernel(const __half* __restrict__ X, __half* __restrict__ out) {
    int t = blockIdx.x * blockDim.x + threadIdx.x;
    int node = t >> 4;
    if (node >= N_NODES) return;
    int lane = t & 15;
    const uint4* Xr = reinterpret_cast<const uint4*>(X);   // 16 uint4 per row

    int beg = __ldg(&g_rowptr[node]);
    int end = __ldg(&g_rowptr[node + 1]);

    uint4 v = __ldg(&Xr[(size_t)node * 16 + lane]);
    float2 a0 = h2f2(v.x), a1 = h2f2(v.y), a2 = h2f2(v.z), a3 = h2f2(v.w);

    int e = beg;
    for (; e + 1 < end; e += 2) {
        int s0 = __ldg(&g_esrc[e]);
        int s1 = __ldg(&g_esrc[e + 1]);
        uint4 u0 = __ldg(&Xr[(size_t)s0 * 16 + lane]);
        uint4 u1 = __ldg(&Xr[(size_t)s1 * 16 + lane]);
        float2 p;
        p = h2f2(u0.x); a0.x += p.x; a0.y += p.y;
        p = h2f2(u0.y); a1.x += p.x; a1.y += p.y;
        p = h2f2(u0.z); a2.x += p.x; a2.y += p.y;
        p = h2f2(u0.w); a3.x += p.x; a3.y += p.y;
        p = h2f2(u1.x); a0.x += p.x; a0.y += p.y;
        p = h2f2(u1.y); a1.x += p.x; a1.y += p.y;
        p = h2f2(u1.z); a2.x += p.x; a2.y += p.y;
        p = h2f2(u1.w); a3.x += p.x; a3.y += p.y;
    }
    if (e < end) {
        int s = __ldg(&g_esrc[e]);
        uint4 u = __ldg(&Xr[(size_t)s * 16 + lane]);
        float2 p;
        p = h2f2(u.x); a0.x += p.x; a0.y += p.y;
        p = h2f2(u.y); a1.x += p.x; a1.y += p.y;
        p = h2f2(u.z); a2.x += p.x; a2.y += p.y;
        p = h2f2(u.w); a3.x += p.x; a3.y += p.y;
    }

    uint4 o;
    o.x = f22h2(a0.x, a0.y);
    o.y = f22h2(a1.x, a1.y);
    o.z = f22h2(a2.x, a2.y);
    o.w = f22h2(a3.x, a3.y);
    reinterpret_cast<uint4*>(out)[(size_t)node * 16 + lane] = o;
}

// ---------------- fp16 B-fragment precompute ----------------
__global__ void wfrag_kernel(const float* __restrict__ W0, const float* __restrict__ W1,
                             const float* __restrict__ W2) {
    int idx = blockIdx.x * blockDim.x + threadIdx.x;
    if (idx >= 3 * BFRAG_PER_LAYER) return;
    int j    = idx & 1;
    int ni   = (idx >> 1) & 7;
    int lane = (idx >> 4) & 31;
    int ks   = (idx >> 9) & 7;
    int wn   = (idx >> 12) & 1;
    int l    = idx >> 13;
    int n  = wn * 64 + ni * 8 + (lane >> 2);
    int k0 = ks * 16 + 2 * (lane & 3) + j * 8;
    const float* W = (l == 0) ? W0 : ((l == 1) ? W1 : W2);
    __half2 h = __floats2half2_rn(__ldg(&W[k0 * CH + n]), __ldg(&W[(k0 + 1) * CH + n]));
    g_bfrag[idx] = *reinterpret_cast<uint32_t*>(&h);
}

// ---------------- fp16 tensor-core GEMM: H = relu(A @ W + b) ----------------
__global__ __launch_bounds__(256, 4)
void gemm_fp16_kernel(const __half* __restrict__ A, const uint4* __restrict__ bfrag4,
                      const float* __restrict__ bias, __half* __restrict__ H, int M) {
    extern __shared__ uint32_t As[];     // BM2 * PAD2 (half2 units, permuted)
    int tid = threadIdx.x;               // 256
    int row0 = blockIdx.x * BM2;

    // A tile -> smem: uint4 = 4 half2; permute half2 index c2 within groups of 8:
    // p(c2) = (c2&~7) + (c2&3)*2 + ((c2>>2)&1)
    for (int i = tid; i < BM2 * 16; i += 256) {
        int r  = i >> 4;
        int c4 = (i & 15) << 2;
        uint4 v = make_uint4(0u, 0u, 0u, 0u);
        if (row0 + r < M)
            v = __ldg(reinterpret_cast<const uint4*>(A + (size_t)(row0 + r) * CH) + (i & 15));
        int base = r * PAD2 + (c4 & ~7) + ((c4 & 4) ? 1 : 0);
        As[base + 0] = v.x;
        As[base + 2] = v.y;
        As[base + 4] = v.z;
        As[base + 6] = v.w;
    }
    __syncthreads();

    int lane = tid & 31;
    int w    = tid >> 5;
    int wm   = w & 3;         // 4 warps along M (32 rows each)
    int wn   = w >> 2;        // 2 warps along N (64 cols each)

    float c[2][8][4];
#pragma unroll
    for (int mi = 0; mi < 2; mi++)
#pragma unroll
        for (int ni = 0; ni < 8; ni++)
#pragma unroll
            for (int j = 0; j < 4; j++) c[mi][ni][j] = 0.f;

    const uint4* bwarp = bfrag4 + ((size_t)wn * 8) * 128 + lane * 4;
    const uint32_t* a_base = As + (wm * 32 + (lane >> 2)) * PAD2 + (lane & 3) * 2;

#pragma unroll
    for (int ks = 0; ks < 8; ks++) {
        uint2 ar0 = *reinterpret_cast<const uint2*>(a_base + ks * 8);
        uint2 ar8 = *reinterpret_cast<const uint2*>(a_base + 8 * PAD2 + ks * 8);
        uint2 br0 = *reinterpret_cast<const uint2*>(a_base + 16 * PAD2 + ks * 8);
        uint2 br8 = *reinterpret_cast<const uint2*>(a_base + 24 * PAD2 + ks * 8);
        const uint4* p = bwarp + ks * 128;
#pragma unroll
        for (int q = 0; q < 4; q++) {
            uint4 bv = __ldg(p + q);
            asm volatile(
                "mma.sync.aligned.m16n8k16.row.col.f32.f16.f16.f32 "
                "{%0,%1,%2,%3}, {%4,%5,%6,%7}, {%8,%9}, {%0,%1,%2,%3};"
                : "+f"(c[0][2*q][0]), "+f"(c[0][2*q][1]), "+f"(c[0][2*q][2]), "+f"(c[0][2*q][3])
                : "r"(ar0.x), "r"(ar8.x), "r"(ar0.y), "r"(ar8.y), "r"(bv.x), "r"(bv.y));
            asm volatile(
                "mma.sync.aligned.m16n8k16.row.col.f32.f16.f16.f32 "
                "{%0,%1,%2,%3}, {%4,%5,%6,%7}, {%8,%9}, {%0,%1,%2,%3};"
                : "+f"(c[1][2*q][0]), "+f"(c[1][2*q][1]), "+f"(c[1][2*q][2]), "+f"(c[1][2*q][3])
                : "r"(br0.x), "r"(br8.x), "r"(br0.y), "r"(br8.y), "r"(bv.x), "r"(bv.y));
            asm volatile(
                "mma.sync.aligned.m16n8k16.row.col.f32.f16.f16.f32 "
                "{%0,%1,%2,%3}, {%4,%5,%6,%7}, {%8,%9}, {%0,%1,%2,%3};"
                : "+f"(c[0][2*q+1][0]), "+f"(c[0][2*q+1][1]), "+f"(c[0][2*q+1][2]), "+f"(c[0][2*q+1][3])
                : "r"(ar0.x), "r"(ar8.x), "r"(ar0.y), "r"(ar8.y), "r"(bv.z), "r"(bv.w));
            asm volatile(
                "mma.sync.aligned.m16n8k16.row.col.f32.f16.f16.f32 "
                "{%0,%1,%2,%3}, {%4,%5,%6,%7}, {%8,%9}, {%0,%1,%2,%3};"
                : "+f"(c[1][2*q+1][0]), "+f"(c[1][2*q+1][1]), "+f"(c[1][2*q+1][2]), "+f"(c[1][2*q+1][3])
                : "r"(br0.x), "r"(br8.x), "r"(br0.y), "r"(br8.y), "r"(bv.z), "r"(bv.w));
        }
    }

    // epilogue: bias + relu -> half2 stores
#pragma unroll
    for (int mi = 0; mi < 2; mi++) {
#pragma unroll
        for (int ni = 0; ni < 8; ni++) {
            int col = wn * 64 + ni * 8 + 2 * (lane & 3);
            float bx = __ldg(&bias[col]), by = __ldg(&bias[col + 1]);
            int r = row0 + wm * 32 + mi * 16 + (lane >> 2);
            if (r < M) {
                __half2 o = __floats2half2_rn(fmaxf(c[mi][ni][0] + bx, 0.f),
                                              fmaxf(c[mi][ni][1] + by, 0.f));
                *reinterpret_cast<__half2*>(H + (size_t)r * CH + col) = o;
            }
            if (r + 8 < M) {
                __half2 o = __floats2half2_rn(fmaxf(c[mi][ni][2] + bx, 0.f),
                                              fmaxf(c[mi][ni][3] + by, 0.f));
                *reinterpret_cast<__half2*>(H + (size_t)(r + 8) * CH + col) = o;
            }
        }
    }
}

// ---------------- pooling + classifier ----------------
__global__ void zero_pool_kernel() {
    int i = blockIdx.x * blockDim.x + threadIdx.x;
    if (i < N_GRAPHS * CH) g_pool[i] = 0.f;
}

__global__ void counts_kernel(const void* __restrict__ batch) {
    int g = blockIdx.x * blockDim.x + threadIdx.x;
    if (g >= N_GRAPHS) return;
    int is64 = g_idx64;
    int lo = 0, hi = N_NODES;
    while (lo < hi) { int m = (lo + hi) >> 1; if (load_idx(batch, m, is64) < g) lo = m + 1; else hi = m; }
    int lb = lo;
    lo = 0; hi = N_NODES;
    while (lo < hi) { int m = (lo + hi) >> 1; if (load_idx(batch, m, is64) <= g) lo = m + 1; else hi = m; }
    g_cnt[g] = (float)(lo - lb);
}

__global__ void pool_kernel(const __half* __restrict__ Hm, const void* __restrict__ batch) {
    int c = threadIdx.x;  // 0..127
    int start = blockIdx.x * 128;
    int end = min(start + 128, N_NODES);
    if (start >= N_NODES) return;
    int is64 = g_idx64;
    long long cur = load_idx(batch, start, is64);
    float sum = 0.f;
    for (int i = start; i < end; i++) {
        long long g = load_idx(batch, i, is64);
        if (g != cur) {
            atomicAdd(&g_pool[(int)cur * CH + c], sum);
            sum = 0.f; cur = g;
        }
        sum += __half2float(Hm[(size_t)i * CH + c]);
    }
    atomicAdd(&g_pool[(int)cur * CH + c], sum);
}

__global__ void final_kernel(const float* __restrict__ Wf, const float* __restrict__ bf,
                             float* __restrict__ out) {
    int g = blockIdx.x;
    int o = threadIdx.x;  // 0..63
    float inv = 1.f / fmaxf(g_cnt[g], 1.f);
    float s = 0.f;
#pragma unroll 8
    for (int k = 0; k < CH; k++)
        s = fmaf(g_pool[g * CH + k], __ldg(&Wf[k * OUTC + o]), s);
    out[g * OUTC + o] = s * inv + bf[o];
}

// ---------------- launch ----------------
extern "C" void kernel_launch(void* const* d_in, const int* in_sizes, int n_in,
                              void* d_out, int out_size) {
    const float* x = nullptr;
    const void* ei = nullptr;
    const void* batch = nullptr;
    const float* Wm[3] = {nullptr, nullptr, nullptr};
    const float* Bv[3] = {nullptr, nullptr, nullptr};
    const float* Wf = nullptr;
    const float* bf = nullptr;
    int wi = 0, bi = 0;
    for (int i = 0; i < n_in; i++) {
        switch (in_sizes[i]) {
            case N_NODES * CH:      x     = (const float*)d_in[i]; break;
            case 2 * N_EDGES:       ei    = d_in[i]; break;
            case N_NODES:           batch = d_in[i]; break;
            case CH * CH:           if (wi < 3) Wm[wi++] = (const float*)d_in[i]; break;
            case CH:                if (bi < 3) Bv[bi++] = (const float*)d_in[i]; break;
            case CH * OUTC:         Wf    = (const float*)d_in[i]; break;
            case OUTC:              bf    = (const float*)d_in[i]; break;
            default: break;
        }
    }
    float* out = (float*)d_out;

    size_t smem = (size_t)(BM2 * PAD2) * sizeof(uint32_t);   // 36864
    cudaFuncSetAttribute(gemm_fp16_kernel, cudaFuncAttributeMaxDynamicSharedMemorySize, (int)smem);

    __half* xh_p;  cudaGetSymbolAddress((void**)&xh_p,  g_xh);
    __half* agg_p; cudaGetSymbolAddress((void**)&agg_p, g_agg);
    __half* h_p;   cudaGetSymbolAddress((void**)&h_p,   g_h);
    uint32_t* bfrag_p; cudaGetSymbolAddress((void**)&bfrag_p, g_bfrag);

    const int node_blocks  = (N_NODES + 255) / 256;
    const int edge4_blocks = (N_EDGES / 4 + 255) / 256;
    const int agg_blocks   = (N_NODES * 16 + 255) / 256;
    const int gemm_blocks  = (N_NODES + BM2 - 1) / BM2;

    // ---- once-per-launch prep
    detect_kernel<<<1, 1>>>((const int*)ei);
    xconv_kernel<<<(N_NODES * CH / 2 + 255) / 256, 256>>>((const float2*)x);
    zero_deg_kernel<<<node_blocks, 256>>>();
    hist_kernel<<<edge4_blocks, 256>>>(ei);
    scan1_kernel<<<SCAN_NB, SCAN_BLK>>>();
    scan2_kernel<<<1, 32>>>();
    scan3_kernel<<<node_blocks, 256>>>();
    fill_kernel<<<edge4_blocks, 256>>>(ei);
    wfrag_kernel<<<(3 * BFRAG_PER_LAYER + 255) / 256, 256>>>(Wm[0], Wm[1], Wm[2]);

    // ---- layer 1
    aggregate_kernel<<<agg_blocks, 256>>>(xh_p, agg_p);
    gemm_fp16_kernel<<<gemm_blocks, 256, smem>>>(agg_p, (const uint4*)(bfrag_p), Bv[0], h_p, N_NODES);

    // ---- layer 2
    aggregate_kernel<<<agg_blocks, 256>>>(h_p, agg_p);
    gemm_fp16_kernel<<<gemm_blocks, 256, smem>>>(agg_p, (const uint4*)(bfrag_p + BFRAG_PER_LAYER), Bv[1], h_p, N_NODES);

    // ---- layer 3
    aggregate_kernel<<<agg_blocks, 256>>>(h_p, agg_p);
    gemm_fp16_kernel<<<gemm_blocks, 256, smem>>>(agg_p, (const uint4*)(bfrag_p + 2 * BFRAG_PER_LAYER), Bv[2], h_p, N_NODES);

    // ---- pooling + classifier
    zero_pool_kernel<<<(N_GRAPHS * CH + 255) / 256, 256>>>();
    counts_kernel<<<1, N_GRAPHS>>>(batch);
    pool_kernel<<<(N_NODES + 127) / 128, 128>>>(h_p, batch);
    final_kernel<<<N_GRAPHS, OUTC>>>(Wf, bf, out);

    (void)n_in; (void)out_size;
}